// round 13
// baseline (speedup 1.0000x reference)
#include <cuda_runtime.h>
#include <cuda_bf16.h>
#include <math.h>
#include <stdint.h>

#define NV 20000
#define NB 4
#define NCF 64
#define VOX 64
#define MROWS (NV*NB)      // 80000
#define MAXW 1024
#define MAXE 131072
#define WT_TOTAL 1433600
#define PLANE ((size_t)MROWS * MAXW)   // bf16 elements per plane

// ---------------- static device scratch ----------------
__device__ __align__(16) __nv_bfloat16 g_actA[2 * PLANE];   // hi plane, lo plane
__device__ __align__(16) __nv_bfloat16 g_actB[2 * PLANE];
__device__ __align__(16) __nv_bfloat16 g_actC[2 * PLANE];
__device__ __align__(16) float g_f32[(size_t)MROWS * 64];
__device__ __align__(16) float g_off[NB * 256];
__device__ __align__(16) __nv_bfloat16 g_WThi[WT_TOTAL];
__device__ __align__(16) __nv_bfloat16 g_WTlo[WT_TOTAL];
__device__ int   g_cnt[NV];
__device__ int   g_cur[NV];
__device__ int   g_rowptr[NV + 1];
__device__ float g_dinv[NV];
__device__ float g_selfw[NV];
__device__ int   g_csrc[MAXE];
__device__ float g_cw[MAXE];

// ---------------- helpers ----------------
__device__ __forceinline__ uint32_t smem_u32(const void* p) {
    uint32_t a;
    asm("{ .reg .u64 t; cvta.to.shared.u64 t, %1; cvt.u32.u64 %0, t; }" : "=r"(a) : "l"(p));
    return a;
}
__device__ __forceinline__ uint32_t pack_bf2(float a, float b) {
    return (uint32_t)__bfloat16_as_ushort(__float2bfloat16_rn(a)) |
           ((uint32_t)__bfloat16_as_ushort(__float2bfloat16_rn(b)) << 16);
}

#define LDMX4(R0, R1, R2, R3, addr)                                              \
    asm volatile("ldmatrix.sync.aligned.m8n8.x4.shared.b16 {%0,%1,%2,%3}, [%4];" \
                 : "=r"(R0), "=r"(R1), "=r"(R2), "=r"(R3) : "r"(addr))

#define MMA_BF16(C, A0, A1, A2, A3, B0, B1)                                      \
    asm volatile("mma.sync.aligned.m16n8k16.row.col.f32.bf16.bf16.f32 "          \
                 "{%0,%1,%2,%3}, {%4,%5,%6,%7}, {%8,%9}, {%0,%1,%2,%3};"         \
                 : "+f"((C)[0]), "+f"((C)[1]), "+f"((C)[2]), "+f"((C)[3])        \
                 : "r"(A0), "r"(A1), "r"(A2), "r"(A3), "r"(B0), "r"(B1))

// ---------------- prep: constant voxel sample + encoder-1 offset ----------------
__global__ void k_prep(const float* __restrict__ feat, const float* __restrict__ W1,
                       const float* __restrict__ b1) {
    __shared__ float s[NB * NCF];
    int t = threadIdx.x;   // 1024
    if (t < NB * NCF) {
        int b = t / NCF, c = t % NCF;
        float vn = -1.0f / 1.5f;
        float x = (vn + 1.0f) * 0.5f * (float)(VOX - 1);
        x = fminf(fmaxf(x, 0.0f), (float)(VOX - 1));
        float x0f = floorf(x);
        float w = x - x0f;
        int i0 = (int)x0f;
        if (i0 < 0) i0 = 0;
        if (i0 > VOX - 1) i0 = VOX - 1;
        int i1 = i0 + 1;
        if (i1 > VOX - 1) i1 = VOX - 1;
        const float* f = feat + (size_t)(b * NCF + c) * VOX * VOX * VOX;
        #define FV(z, y, xx) f[((z) * VOX + (y)) * VOX + (xx)]
        float c00 = FV(i0, i0, i0) * (1.0f - w) + FV(i0, i0, i1) * w;
        float c01 = FV(i0, i1, i0) * (1.0f - w) + FV(i0, i1, i1) * w;
        float c10 = FV(i1, i0, i0) * (1.0f - w) + FV(i1, i0, i1) * w;
        float c11 = FV(i1, i1, i0) * (1.0f - w) + FV(i1, i1, i1) * w;
        #undef FV
        float c0 = c00 * (1.0f - w) + c01 * w;
        float c1 = c10 * (1.0f - w) + c11 * w;
        s[t] = c0 * (1.0f - w) + c1 * w;
    }
    __syncthreads();
    int b = t >> 8, j = t & 255;
    float acc = b1[j];
    #pragma unroll 8
    for (int c = 0; c < NCF; c++)
        acc += s[b * NCF + c] * W1[(3 + c) * 256 + j];
    g_off[t] = acc;
}

// encoder layer 1: writes split bf16 planes into g_actA (K=256)
__global__ void k_enc1(const float* __restrict__ V, const float* __restrict__ W1) {
    int row = blockIdx.x;
    int j = threadIdx.x;
    int n = row >> 2, b = row & 3;
    float vx = V[n * 3 + 0], vy = V[n * 3 + 1], vz = V[n * 3 + 2];
    float acc = g_off[b * 256 + j] + vx * W1[j] + vy * W1[256 + j] + vz * W1[512 + j];
    acc = fmaxf(acc, 0.0f);
    __nv_bfloat16 h = __float2bfloat16_rn(acc);
    g_actA[(size_t)row * 256 + j] = h;
    g_actA[PLANE + (size_t)row * 256 + j] = __float2bfloat16_rn(acc - __bfloat162float(h));
}

// ---------------- weight transpose + bf16 hi/lo split ----------------
__global__ void k_wsplit(const float* __restrict__ W, int K, int N,
                         __nv_bfloat16* __restrict__ hi, __nv_bfloat16* __restrict__ lo) {
    int idx = blockIdx.x * 256 + threadIdx.x;
    if (idx >= N * K) return;
    int n = idx / K, k = idx - n * K;
    float v = W[k * N + n];
    __nv_bfloat16 h = __float2bfloat16_rn(v);
    hi[idx] = h;
    lo[idx] = __float2bfloat16_rn(v - __bfloat162float(h));
}

// ---------------- graph preprocessing ----------------
__global__ void k_zero() {
    int i = blockIdx.x * 256 + threadIdx.x;
    if (i < NV) { g_cnt[i] = 0; g_cur[i] = 0; }
}
__global__ void k_count(const int* __restrict__ dst, int E) {
    int e = blockIdx.x * 256 + threadIdx.x;
    if (e < E) atomicAdd(&g_cnt[dst[e]], 1);
}
__global__ void k_scan() {
    __shared__ int part[1024];
    int t = threadIdx.x;
    const int SEG = 20;
    int base = t * SEG;
    int s = 0;
    for (int i = 0; i < SEG; i++) {
        int idx = base + i;
        if (idx < NV) s += g_cnt[idx];
    }
    part[t] = s;
    __syncthreads();
    for (int off = 1; off < 1024; off <<= 1) {
        int v = (t >= off) ? part[t - off] : 0;
        __syncthreads();
        part[t] += v;
        __syncthreads();
    }
    int run = (t == 0) ? 0 : part[t - 1];
    for (int i = 0; i < SEG; i++) {
        int idx = base + i;
        if (idx < NV) { g_rowptr[idx] = run; run += g_cnt[idx]; }
    }
    if (t == 1023) g_rowptr[NV] = part[1023];
}
__global__ void k_dinv() {
    int n = blockIdx.x * 256 + threadIdx.x;
    if (n < NV) {
        float d = (float)g_cnt[n] + 1.0f;
        float di = 1.0f / sqrtf(d);
        g_dinv[n] = di;
        g_selfw[n] = di * di;
    }
}
__global__ void k_fill(const int* __restrict__ src, const int* __restrict__ dst, int E) {
    int e = blockIdx.x * 256 + threadIdx.x;
    if (e >= E) return;
    int s = src[e], d = dst[e];
    int slot = atomicAdd(&g_cur[d], 1);
    int p = g_rowptr[d] + slot;
    g_csrc[p] = s;
    g_cw[p] = g_dinv[s] * g_dinv[d];
}
__global__ void k_sort() {
    int n = blockIdx.x * 256 + threadIdx.x;
    if (n >= NV) return;
    int a = g_rowptr[n], bnd = g_rowptr[n + 1];
    for (int i = a + 1; i < bnd; i++) {
        int key = g_csrc[i]; float kw = g_cw[i];
        int j = i - 1;
        while (j >= a && g_csrc[j] > key) {
            g_csrc[j + 1] = g_csrc[j]; g_cw[j + 1] = g_cw[j]; j--;
        }
        g_csrc[j + 1] = key; g_cw[j + 1] = kw;
    }
}

// ---------------- bf16x3 mma GEMM: CTA 256x128, 16 warps @ 64x32, BK=32 ----------------
// A: split bf16 planes [M][K]. W: split [N][K].
#define RSTRIDE 80
#define A_PL    20480          // 256 rows * 80
#define B_PL    10240          // 128 rows * 80
#define AHI_OFF 0
#define ALO_OFF 20480
#define BHI_OFF 40960
#define BLO_OFF 51200
#define STAGEB  61440
#define GEMM_SMEM (2 * STAGEB)

__global__ __launch_bounds__(512, 1)
void k_gemm(const __nv_bfloat16* __restrict__ Abase, const __nv_bfloat16* __restrict__ Whi,
            const __nv_bfloat16* __restrict__ Wlo, void* __restrict__ Cptr,
            int K, int N, const float* __restrict__ bias, int relu, int splitout) {
    extern __shared__ char smem[];
    uint32_t sb = smem_u32(smem);
    const __nv_bfloat16* Ahi = Abase;
    const __nv_bfloat16* Alo = Abase + PLANE;
    int tid = threadIdx.x;
    int warp = tid >> 5, lane = tid & 31;
    int gid = lane >> 2, ctid = lane & 3;
    int wm = warp & 3;       // 4 slabs of 64 rows (256 total)
    int wn = warp >> 2;      // 4 slabs of 32 cols (128 total)
    int bm = blockIdx.y * 256;
    int bn = blockIdx.x * 128;

    // ldmatrix lane addressing
    int aLr = (lane & 7) + ((lane >> 3) & 1) * 8;
    int aLk = (lane >> 4) * 16;
    int aBase = (wm * 64 + aLr) * RSTRIDE + aLk;
    int bLr = (lane & 7) + (lane >> 4) * 8;
    int bLk = ((lane >> 3) & 1) * 16;
    int bBase = (wn * 32 + bLr) * RSTRIDE + bLk;

    float acc[4][4][4];
    #pragma unroll
    for (int i = 0; i < 4; i++)
        #pragma unroll
        for (int j = 0; j < 4; j++)
            #pragma unroll
            for (int f = 0; f < 4; f++) acc[i][j][f] = 0.0f;

    // staging: A 2048 float4 (both planes), B 1024 float4 -> 4 + 2 per thread
    float4 aP[4], bP[2];
    #pragma unroll
    for (int i = 0; i < 4; i++) {
        int f = tid + (i << 9);
        int plane = f >> 10, rem = f & 1023;
        int row = rem >> 2, kc = rem & 3;
        int grow = bm + row;
        if (grow >= MROWS) grow = MROWS - 1;      // clamp (values unused)
        const __nv_bfloat16* Ap = plane ? Alo : Ahi;
        aP[i] = *reinterpret_cast<const float4*>((const char*)(Ap + (size_t)grow * K) + kc * 16);
    }
    #pragma unroll
    for (int i = 0; i < 2; i++) {
        int f = tid + (i << 9);
        int plane = f >> 9, rem = f & 511;
        int row = rem >> 2, kc = rem & 3;
        const __nv_bfloat16* Wp = plane ? Wlo : Whi;
        if (bn + row < N)
            bP[i] = *reinterpret_cast<const float4*>((const char*)(Wp + (size_t)(bn + row) * K) + kc * 16);
        else
            bP[i] = make_float4(0.f, 0.f, 0.f, 0.f);
    }

    int T = K >> 5;
    for (int t = 0; t < T; t++) {
        char* base = smem + (t & 1) * STAGEB;
        uint32_t sbase = sb + (t & 1) * STAGEB;
        // stage regs -> smem (pure copy)
        #pragma unroll
        for (int i = 0; i < 4; i++) {
            int f = tid + (i << 9);
            int plane = f >> 10, rem = f & 1023;
            int row = rem >> 2, kc = rem & 3;
            *reinterpret_cast<float4*>(base + (plane ? ALO_OFF : AHI_OFF) + row * RSTRIDE + kc * 16) = aP[i];
        }
        #pragma unroll
        for (int i = 0; i < 2; i++) {
            int f = tid + (i << 9);
            int plane = f >> 9, rem = f & 511;
            int row = rem >> 2, kc = rem & 3;
            *reinterpret_cast<float4*>(base + (plane ? BLO_OFF : BHI_OFF) + row * RSTRIDE + kc * 16) = bP[i];
        }
        __syncthreads();

        // prefetch t+1
        if (t + 1 < T) {
            int kt = (t + 1) << 5;
            #pragma unroll
            for (int i = 0; i < 4; i++) {
                int f = tid + (i << 9);
                int plane = f >> 10, rem = f & 1023;
                int row = rem >> 2, kc = rem & 3;
                int grow = bm + row;
                if (grow >= MROWS) grow = MROWS - 1;
                const __nv_bfloat16* Ap = plane ? Alo : Ahi;
                aP[i] = *reinterpret_cast<const float4*>((const char*)(Ap + (size_t)grow * K + kt) + kc * 16);
            }
            #pragma unroll
            for (int i = 0; i < 2; i++) {
                int f = tid + (i << 9);
                int plane = f >> 9, rem = f & 511;
                int row = rem >> 2, kc = rem & 3;
                const __nv_bfloat16* Wp = plane ? Wlo : Whi;
                if (bn + row < N)
                    bP[i] = *reinterpret_cast<const float4*>((const char*)(Wp + (size_t)(bn + row) * K + kt) + kc * 16);
                else
                    bP[i] = make_float4(0.f, 0.f, 0.f, 0.f);
            }
        }

        // compute 2 k16-steps
        #pragma unroll
        for (int ks = 0; ks < 2; ks++) {
            int k2 = ks * 32;
            uint32_t bh[4][2], bl[4][2];
            #pragma unroll
            for (int p = 0; p < 2; p++) {
                LDMX4(bh[2 * p][0], bh[2 * p][1], bh[2 * p + 1][0], bh[2 * p + 1][1],
                      sbase + BHI_OFF + bBase + p * (16 * RSTRIDE) + k2);
                LDMX4(bl[2 * p][0], bl[2 * p][1], bl[2 * p + 1][0], bl[2 * p + 1][1],
                      sbase + BLO_OFF + bBase + p * (16 * RSTRIDE) + k2);
            }
            #pragma unroll
            for (int mi = 0; mi < 4; mi++) {
                uint32_t ah[4], al[4];
                LDMX4(ah[0], ah[1], ah[2], ah[3],
                      sbase + AHI_OFF + aBase + mi * (16 * RSTRIDE) + k2);
                LDMX4(al[0], al[1], al[2], al[3],
                      sbase + ALO_OFF + aBase + mi * (16 * RSTRIDE) + k2);
                #pragma unroll
                for (int ni = 0; ni < 4; ni++) {
                    MMA_BF16(acc[mi][ni], ah[0], ah[1], ah[2], ah[3], bh[ni][0], bh[ni][1]);
                    MMA_BF16(acc[mi][ni], ah[0], ah[1], ah[2], ah[3], bl[ni][0], bl[ni][1]);
                    MMA_BF16(acc[mi][ni], al[0], al[1], al[2], al[3], bh[ni][0], bh[ni][1]);
                }
            }
        }
        if (t + 1 < T) __syncthreads();
    }

    // epilogue
    #pragma unroll
    for (int mi = 0; mi < 4; mi++) {
        int gm0 = bm + wm * 64 + mi * 16 + gid;
        if (gm0 + 8 >= MROWS && gm0 >= MROWS) continue;
        #pragma unroll
        for (int ni = 0; ni < 4; ni++) {
            int gc = bn + wn * 32 + ni * 8 + 2 * ctid;
            if (gc < N) {
                float bx = 0.f, by = 0.f;
                if (bias) { bx = bias[gc]; by = bias[gc + 1]; }
                float v0 = acc[mi][ni][0] + bx, v1 = acc[mi][ni][1] + by;
                float v2 = acc[mi][ni][2] + bx, v3 = acc[mi][ni][3] + by;
                if (relu) {
                    v0 = fmaxf(v0, 0.f); v1 = fmaxf(v1, 0.f);
                    v2 = fmaxf(v2, 0.f); v3 = fmaxf(v3, 0.f);
                }
                if (splitout) {
                    __nv_bfloat16* Chi = (__nv_bfloat16*)Cptr;
                    __nv_bfloat16* Clo = Chi + PLANE;
                    uint32_t h01 = pack_bf2(v0, v1);
                    uint32_t h23 = pack_bf2(v2, v3);
                    float r0 = v0 - __uint_as_float(h01 << 16);
                    float r1 = v1 - __uint_as_float(h01 & 0xFFFF0000u);
                    float r2 = v2 - __uint_as_float(h23 << 16);
                    float r3 = v3 - __uint_as_float(h23 & 0xFFFF0000u);
                    if (gm0 < MROWS) {
                        *reinterpret_cast<uint32_t*>(Chi + (size_t)gm0 * N + gc) = h01;
                        *reinterpret_cast<uint32_t*>(Clo + (size_t)gm0 * N + gc) = pack_bf2(r0, r1);
                    }
                    if (gm0 + 8 < MROWS) {
                        *reinterpret_cast<uint32_t*>(Chi + (size_t)(gm0 + 8) * N + gc) = h23;
                        *reinterpret_cast<uint32_t*>(Clo + (size_t)(gm0 + 8) * N + gc) = pack_bf2(r2, r3);
                    }
                } else {
                    float* C = (float*)Cptr;
                    if (gm0 < MROWS)
                        *reinterpret_cast<float2*>(C + (size_t)gm0 * N + gc) = make_float2(v0, v1);
                    if (gm0 + 8 < MROWS)
                        *reinterpret_cast<float2*>(C + (size_t)(gm0 + 8) * N + gc) = make_float2(v2, v3);
                }
            }
        }
    }
}

// ---------------- GCN aggregate on split planes ----------------
__device__ __forceinline__ void unpack8(uint4 h, uint4 l, float* v) {
    const uint32_t* hp = (const uint32_t*)&h;
    const uint32_t* lp = (const uint32_t*)&l;
    #pragma unroll
    for (int j = 0; j < 4; j++) {
        v[2 * j]     = __uint_as_float(hp[j] << 16)        + __uint_as_float(lp[j] << 16);
        v[2 * j + 1] = __uint_as_float(hp[j] & 0xFFFF0000u) + __uint_as_float(lp[j] & 0xFFFF0000u);
    }
}

__global__ void k_agg(const __nv_bfloat16* __restrict__ H, __nv_bfloat16* __restrict__ X,
                      const float* __restrict__ bias, int Cout, int relu) {
    int n = blockIdx.y;
    int C8 = (NB * Cout) >> 3;   // 16B groups per node-row
    int i = blockIdx.x * blockDim.x + threadIdx.x;
    if (i >= C8) return;
    const uint4* Hh = (const uint4*)H;
    const uint4* Hl = (const uint4*)(H + PLANE);
    uint4* Xh = (uint4*)X;
    uint4* Xl = (uint4*)(X + PLANE);

    float acc[8];
    float sw = g_selfw[n];
    size_t base = (size_t)n * C8 + i;
    {
        float v[8];
        unpack8(Hh[base], Hl[base], v);
        if (bias) {
            int b = (8 * i) / Cout;
            int c0 = 8 * i - b * Cout;
            #pragma unroll
            for (int j = 0; j < 8; j++) acc[j] = v[j] * sw + bias[c0 + j];
        } else {
            #pragma unroll
            for (int j = 0; j < 8; j++) acc[j] = v[j] * sw;
        }
    }
    int e0 = g_rowptr[n], e1 = g_rowptr[n + 1];
    for (int e = e0; e < e1; e++) {
        int s = g_csrc[e];
        float w = g_cw[e];
        float v[8];
        unpack8(Hh[(size_t)s * C8 + i], Hl[(size_t)s * C8 + i], v);
        #pragma unroll
        for (int j = 0; j < 8; j++) acc[j] += v[j] * w;
    }
    if (relu) {
        #pragma unroll
        for (int j = 0; j < 8; j++) acc[j] = fmaxf(acc[j], 0.0f);
    }
    uint4 oh, ol;
    uint32_t* ohp = (uint32_t*)&oh;
    uint32_t* olp = (uint32_t*)&ol;
    #pragma unroll
    for (int j = 0; j < 4; j++) {
        uint32_t hp_ = pack_bf2(acc[2 * j], acc[2 * j + 1]);
        float r0 = acc[2 * j]     - __uint_as_float(hp_ << 16);
        float r1 = acc[2 * j + 1] - __uint_as_float(hp_ & 0xFFFF0000u);
        ohp[j] = hp_;
        olp[j] = pack_bf2(r0, r1);
    }
    Xh[base] = oh;
    Xl[base] = ol;
}

// ---------------- head layer 3 ----------------
__global__ void k_head3(const float* __restrict__ D, const float* __restrict__ W3,
                        const float* __restrict__ b3, const float* __restrict__ V,
                        float* __restrict__ out) {
    int r = blockIdx.x * blockDim.x + threadIdx.x;
    if (r >= MROWS) return;
    int n = r >> 2, b = r & 3;
    const float* d = D + (size_t)r * 64;
    float y0 = b3[0], y1 = b3[1], y2 = b3[2];
    #pragma unroll 8
    for (int c = 0; c < 64; c++) {
        float v = d[c];
        y0 += v * W3[c * 3 + 0];
        y1 += v * W3[c * 3 + 1];
        y2 += v * W3[c * 3 + 2];
    }
    float ys[3] = {y0, y1, y2};
    #pragma unroll
    for (int k = 0; k < 3; k++) {
        float y = tanhf(ys[k]);
        if (isnan(y)) y = 0.0f;
        y = fminf(fmaxf(y, -2.5f), 2.5f);
        out[((size_t)b * NV + n) * 3 + k] = V[n * 3 + k] + y;
    }
}

// ---------------- host driver ----------------
extern "C" void kernel_launch(void* const* d_in, const int* in_sizes, int n_in,
                              void* d_out, int out_size) {
    const float* feat  = (const float*)d_in[0];
    const float* verts = (const float*)d_in[1];
    const int*   eidx  = (const int*)d_in[2];
    int E = in_sizes[2] / 2;
    if (E > MAXE) E = MAXE;
    const int* esrc = eidx;
    const int* edst = eidx + E;
    const float* encW1 = (const float*)d_in[3];
    const float* encb1 = (const float*)d_in[4];
    const float* encW2 = (const float*)d_in[5];
    const float* encb2 = (const float*)d_in[6];
    const float* gW[6] = {(const float*)d_in[7],  (const float*)d_in[9],
                          (const float*)d_in[11], (const float*)d_in[13],
                          (const float*)d_in[15], (const float*)d_in[17]};
    const float* gb[6] = {(const float*)d_in[8],  (const float*)d_in[10],
                          (const float*)d_in[12], (const float*)d_in[14],
                          (const float*)d_in[16], (const float*)d_in[18]};
    const float* hW1 = (const float*)d_in[19];
    const float* hb1 = (const float*)d_in[20];
    const float* hW2 = (const float*)d_in[21];
    const float* hb2 = (const float*)d_in[22];
    const float* hW3 = (const float*)d_in[23];
    const float* hb3 = (const float*)d_in[24];

    __nv_bfloat16 *actA, *actB, *actC, *wthi, *wtlo;
    float* f32buf;
    cudaGetSymbolAddress((void**)&actA, g_actA);
    cudaGetSymbolAddress((void**)&actB, g_actB);
    cudaGetSymbolAddress((void**)&actC, g_actC);
    cudaGetSymbolAddress((void**)&f32buf, g_f32);
    cudaGetSymbolAddress((void**)&wthi, g_WThi);
    cudaGetSymbolAddress((void**)&wtlo, g_WTlo);

    cudaFuncSetAttribute(k_gemm, cudaFuncAttributeMaxDynamicSharedMemorySize, GEMM_SMEM);

    const int woff[9] = {0, 32768, 65536, 196608, 720896, 1245184, 1376256, 1409024, 1425408};
    const int wk[9]   = {256, 128, 256, 512, 1024, 512, 256, 128, 128};
    const int wn[9]   = {128, 256, 512, 1024, 512, 256, 128, 128, 64};
    const float* wptr[9] = {encW2, gW[0], gW[1], gW[2], gW[3], gW[4], gW[5], hW1, hW2};

    const int MT256 = (MROWS + 255) / 256;   // 313

    auto gemm = [&](const __nv_bfloat16* A, int li, void* C, const float* bias,
                    int relu, int splitout) {
        dim3 grid((wn[li] + 127) / 128, MT256);
        k_gemm<<<grid, 512, GEMM_SMEM>>>(A, wthi + woff[li], wtlo + woff[li], C,
                                         wk[li], wn[li], bias, relu, splitout);
    };
    auto agg = [&](const __nv_bfloat16* H, __nv_bfloat16* X, const float* bias,
                   int Cout, int relu) {
        int C8 = (NB * Cout) >> 3;
        k_agg<<<dim3((C8 + 127) / 128, NV), 128>>>(H, X, bias, Cout, relu);
    };

    // launch order: #4 = first big GEMM (ncu capture window)
    k_prep<<<1, 1024>>>(feat, encW1, encb1);                                  // 1
    k_wsplit<<<(wn[0] * wk[0] + 255) / 256, 256>>>(wptr[0], wk[0], wn[0],
                                                   wthi + woff[0], wtlo + woff[0]); // 2
    k_enc1<<<MROWS, 256>>>(verts, encW1);                                     // 3
    gemm(actA, 0, actB, encb2, 1, 1);                                         // 4 (profiled)

    for (int li = 1; li < 9; li++)
        k_wsplit<<<(wn[li] * wk[li] + 255) / 256, 256>>>(wptr[li], wk[li], wn[li],
                                                         wthi + woff[li], wtlo + woff[li]);
    k_zero<<<(NV + 255) / 256, 256>>>();
    k_count<<<(E + 255) / 256, 256>>>(edst, E);
    k_scan<<<1, 1024>>>();
    k_dinv<<<(NV + 255) / 256, 256>>>();
    k_fill<<<(E + 255) / 256, 256>>>(esrc, edst, E);
    k_sort<<<(NV + 255) / 256, 256>>>();

    // g1..g3: aggregate-then-GEMM (Cin < Cout); bias+relu fused in GEMM
    agg(actB, actC, (const float*)0, 128, 0);
    gemm(actC, 1, actA, gb[0], 1, 1);
    agg(actA, actB, (const float*)0, 256, 0);
    gemm(actB, 2, actC, gb[1], 1, 1);
    agg(actC, actA, (const float*)0, 512, 0);
    gemm(actA, 3, actB, gb[2], 1, 1);
    // g4..g6: GEMM-then-aggregate (Cout < Cin); bias+relu fused in aggregate
    gemm(actB, 4, actC, (const float*)0, 0, 1);
    agg(actC, actA, gb[3], 512, 1);
    gemm(actA, 5, actB, (const float*)0, 0, 1);
    agg(actB, actC, gb[4], 256, 1);
    gemm(actC, 6, actA, (const float*)0, 0, 1);
    agg(actA, actB, gb[5], 128, 1);
    // head
    gemm(actB, 7, actC, hb1, 1, 1);
    gemm(actC, 8, f32buf, hb2, 1, 0);
    k_head3<<<(MROWS + 255) / 256, 256>>>(f32buf, hW3, hb3, verts, (float*)d_out);
}

// round 14
// speedup vs baseline: 1.1353x; 1.1353x over previous
#include <cuda_runtime.h>
#include <cuda_bf16.h>
#include <math.h>
#include <stdint.h>

#define NV 20000
#define NB 4
#define NCF 64
#define VOX 64
#define MROWS (NV*NB)      // 80000
#define MTILES (MROWS/128) // 625
#define MAXW 1024
#define MAXE 131072
#define WT_TOTAL 1433600
#define PLANE ((size_t)MROWS * MAXW)   // bf16 elements per plane

// ---------------- static device scratch ----------------
__device__ __align__(16) __nv_bfloat16 g_actA[2 * PLANE];   // hi plane, lo plane
__device__ __align__(16) __nv_bfloat16 g_actB[2 * PLANE];
__device__ __align__(16) __nv_bfloat16 g_actC[2 * PLANE];
__device__ __align__(16) float g_f32[(size_t)MROWS * 64];
__device__ __align__(16) float g_off[NB * 256];
__device__ __align__(16) __nv_bfloat16 g_WThi[WT_TOTAL];
__device__ __align__(16) __nv_bfloat16 g_WTlo[WT_TOTAL];
__device__ int   g_cnt[NV];
__device__ int   g_cur[NV];
__device__ int   g_rowptr[NV + 1];
__device__ float g_dinv[NV];
__device__ float g_selfw[NV];
__device__ int   g_csrc[MAXE];
__device__ float g_cw[MAXE];

// ---------------- helpers ----------------
__device__ __forceinline__ uint32_t smem_u32(const void* p) {
    uint32_t a;
    asm("{ .reg .u64 t; cvta.to.shared.u64 t, %1; cvt.u32.u64 %0, t; }" : "=r"(a) : "l"(p));
    return a;
}
__device__ __forceinline__ uint32_t pack_bf2(float a, float b) {
    return (uint32_t)__bfloat16_as_ushort(__float2bfloat16_rn(a)) |
           ((uint32_t)__bfloat16_as_ushort(__float2bfloat16_rn(b)) << 16);
}

#define LDMX4(R0, R1, R2, R3, addr)                                              \
    asm volatile("ldmatrix.sync.aligned.m8n8.x4.shared.b16 {%0,%1,%2,%3}, [%4];" \
                 : "=r"(R0), "=r"(R1), "=r"(R2), "=r"(R3) : "r"(addr))

#define MMA_BF16(C, A0, A1, A2, A3, B0, B1)                                      \
    asm volatile("mma.sync.aligned.m16n8k16.row.col.f32.bf16.bf16.f32 "          \
                 "{%0,%1,%2,%3}, {%4,%5,%6,%7}, {%8,%9}, {%0,%1,%2,%3};"         \
                 : "+f"((C)[0]), "+f"((C)[1]), "+f"((C)[2]), "+f"((C)[3])        \
                 : "r"(A0), "r"(A1), "r"(A2), "r"(A3), "r"(B0), "r"(B1))

// ---------------- prep: constant voxel sample + encoder-1 offset ----------------
__global__ void k_prep(const float* __restrict__ feat, const float* __restrict__ W1,
                       const float* __restrict__ b1) {
    __shared__ float s[NB * NCF];
    int t = threadIdx.x;   // 1024
    if (t < NB * NCF) {
        int b = t / NCF, c = t % NCF;
        float vn = -1.0f / 1.5f;
        float x = (vn + 1.0f) * 0.5f * (float)(VOX - 1);
        x = fminf(fmaxf(x, 0.0f), (float)(VOX - 1));
        float x0f = floorf(x);
        float w = x - x0f;
        int i0 = (int)x0f;
        if (i0 < 0) i0 = 0;
        if (i0 > VOX - 1) i0 = VOX - 1;
        int i1 = i0 + 1;
        if (i1 > VOX - 1) i1 = VOX - 1;
        const float* f = feat + (size_t)(b * NCF + c) * VOX * VOX * VOX;
        #define FV(z, y, xx) f[((z) * VOX + (y)) * VOX + (xx)]
        float c00 = FV(i0, i0, i0) * (1.0f - w) + FV(i0, i0, i1) * w;
        float c01 = FV(i0, i1, i0) * (1.0f - w) + FV(i0, i1, i1) * w;
        float c10 = FV(i1, i0, i0) * (1.0f - w) + FV(i1, i0, i1) * w;
        float c11 = FV(i1, i1, i0) * (1.0f - w) + FV(i1, i1, i1) * w;
        #undef FV
        float c0 = c00 * (1.0f - w) + c01 * w;
        float c1 = c10 * (1.0f - w) + c11 * w;
        s[t] = c0 * (1.0f - w) + c1 * w;
    }
    __syncthreads();
    int b = t >> 8, j = t & 255;
    float acc = b1[j];
    #pragma unroll 8
    for (int c = 0; c < NCF; c++)
        acc += s[b * NCF + c] * W1[(3 + c) * 256 + j];
    g_off[t] = acc;
}

// encoder layer 1: writes split bf16 planes into g_actA (K=256)
__global__ void k_enc1(const float* __restrict__ V, const float* __restrict__ W1) {
    int row = blockIdx.x;
    int j = threadIdx.x;
    int n = row >> 2, b = row & 3;
    float vx = V[n * 3 + 0], vy = V[n * 3 + 1], vz = V[n * 3 + 2];
    float acc = g_off[b * 256 + j] + vx * W1[j] + vy * W1[256 + j] + vz * W1[512 + j];
    acc = fmaxf(acc, 0.0f);
    __nv_bfloat16 h = __float2bfloat16_rn(acc);
    g_actA[(size_t)row * 256 + j] = h;
    g_actA[PLANE + (size_t)row * 256 + j] = __float2bfloat16_rn(acc - __bfloat162float(h));
}

// ---------------- weight transpose + bf16 hi/lo split ----------------
__global__ void k_wsplit(const float* __restrict__ W, int K, int N,
                         __nv_bfloat16* __restrict__ hi, __nv_bfloat16* __restrict__ lo) {
    int idx = blockIdx.x * 256 + threadIdx.x;
    if (idx >= N * K) return;
    int n = idx / K, k = idx - n * K;
    float v = W[k * N + n];
    __nv_bfloat16 h = __float2bfloat16_rn(v);
    hi[idx] = h;
    lo[idx] = __float2bfloat16_rn(v - __bfloat162float(h));
}

// ---------------- graph preprocessing ----------------
__global__ void k_zero() {
    int i = blockIdx.x * 256 + threadIdx.x;
    if (i < NV) { g_cnt[i] = 0; g_cur[i] = 0; }
}
__global__ void k_count(const int* __restrict__ dst, int E) {
    int e = blockIdx.x * 256 + threadIdx.x;
    if (e < E) atomicAdd(&g_cnt[dst[e]], 1);
}
__global__ void k_scan() {
    __shared__ int part[1024];
    int t = threadIdx.x;
    const int SEG = 20;
    int base = t * SEG;
    int s = 0;
    for (int i = 0; i < SEG; i++) {
        int idx = base + i;
        if (idx < NV) s += g_cnt[idx];
    }
    part[t] = s;
    __syncthreads();
    for (int off = 1; off < 1024; off <<= 1) {
        int v = (t >= off) ? part[t - off] : 0;
        __syncthreads();
        part[t] += v;
        __syncthreads();
    }
    int run = (t == 0) ? 0 : part[t - 1];
    for (int i = 0; i < SEG; i++) {
        int idx = base + i;
        if (idx < NV) { g_rowptr[idx] = run; run += g_cnt[idx]; }
    }
    if (t == 1023) g_rowptr[NV] = part[1023];
}
__global__ void k_dinv() {
    int n = blockIdx.x * 256 + threadIdx.x;
    if (n < NV) {
        float d = (float)g_cnt[n] + 1.0f;
        float di = 1.0f / sqrtf(d);
        g_dinv[n] = di;
        g_selfw[n] = di * di;
    }
}
__global__ void k_fill(const int* __restrict__ src, const int* __restrict__ dst, int E) {
    int e = blockIdx.x * 256 + threadIdx.x;
    if (e >= E) return;
    int s = src[e], d = dst[e];
    int slot = atomicAdd(&g_cur[d], 1);
    int p = g_rowptr[d] + slot;
    g_csrc[p] = s;
    g_cw[p] = g_dinv[s] * g_dinv[d];
}
__global__ void k_sort() {
    int n = blockIdx.x * 256 + threadIdx.x;
    if (n >= NV) return;
    int a = g_rowptr[n], bnd = g_rowptr[n + 1];
    for (int i = a + 1; i < bnd; i++) {
        int key = g_csrc[i]; float kw = g_cw[i];
        int j = i - 1;
        while (j >= a && g_csrc[j] > key) {
            g_csrc[j + 1] = g_csrc[j]; g_cw[j + 1] = g_cw[j]; j--;
        }
        g_csrc[j + 1] = key; g_cw[j + 1] = kw;
    }
}

// ---------------- bf16x3 mma GEMM: 128x128, 16 warps @ 32x32, BK=64 ----------------
// A: split bf16 planes [M][K] (hi at Abase, lo at Abase+PLANE). W: split [N][K].
// Single sync per chunk (double-buffer + staging-from-registers makes the 2nd sync redundant);
// B fragments software-pipelined across k16-steps.
#define RSTRIDE 144
#define AHI_OFF 0
#define ALO_OFF 18432
#define BHI_OFF 36864
#define BLO_OFF 55296
#define STAGEB  73728
#define GEMM_SMEM (2 * STAGEB)

__global__ __launch_bounds__(512, 1)
void k_gemm(const __nv_bfloat16* __restrict__ Abase, const __nv_bfloat16* __restrict__ Whi,
            const __nv_bfloat16* __restrict__ Wlo, void* __restrict__ Cptr,
            int K, int N, const float* __restrict__ bias, int relu, int splitout) {
    extern __shared__ char smem[];
    uint32_t sb = smem_u32(smem);
    const __nv_bfloat16* Ahi = Abase;
    const __nv_bfloat16* Alo = Abase + PLANE;
    int tid = threadIdx.x;
    int warp = tid >> 5, lane = tid & 31;
    int gid = lane >> 2, ctid = lane & 3;
    int wm = warp & 3;       // 4 slabs of 32 rows
    int wn = warp >> 2;      // 4 slabs of 32 cols
    int bm = blockIdx.y * 128;
    int bn = blockIdx.x * 128;

    // ldmatrix lane addressing
    int aLr = (lane & 7) + ((lane >> 3) & 1) * 8;
    int aLk = (lane >> 4) * 16;
    int aBase = (wm * 32 + aLr) * RSTRIDE + aLk;
    int bLr = (lane & 7) + (lane >> 4) * 8;
    int bLk = ((lane >> 3) & 1) * 16;
    int bBase = (wn * 32 + bLr) * RSTRIDE + bLk;

    float acc[2][4][4];
    #pragma unroll
    for (int i = 0; i < 2; i++)
        #pragma unroll
        for (int j = 0; j < 4; j++)
            #pragma unroll
            for (int f = 0; f < 4; f++) acc[i][j][f] = 0.0f;

    float4 aP[4], bP[4];
    // prefetch t=0
    #pragma unroll
    for (int i = 0; i < 4; i++) {
        int f = tid + (i << 9);
        int plane = f >> 10, rem = f & 1023;
        int row = rem >> 3, kc = rem & 7;
        const __nv_bfloat16* Ap = plane ? Alo : Ahi;
        aP[i] = *reinterpret_cast<const float4*>((const char*)(Ap + (size_t)(bm + row) * K) + kc * 16);
        const __nv_bfloat16* Wp = plane ? Wlo : Whi;
        if (bn + row < N)
            bP[i] = *reinterpret_cast<const float4*>((const char*)(Wp + (size_t)(bn + row) * K) + kc * 16);
        else
            bP[i] = make_float4(0.f, 0.f, 0.f, 0.f);
    }

    int T = K >> 6;
    for (int t = 0; t < T; t++) {
        char* base = smem + (t & 1) * STAGEB;
        uint32_t sbase = sb + (t & 1) * STAGEB;
        // stage regs -> smem (pure copy)
        #pragma unroll
        for (int i = 0; i < 4; i++) {
            int f = tid + (i << 9);
            int plane = f >> 10, rem = f & 1023;
            int row = rem >> 3, kc = rem & 7;
            int off = row * RSTRIDE + kc * 16;
            *reinterpret_cast<float4*>(base + (plane ? ALO_OFF : AHI_OFF) + off) = aP[i];
            *reinterpret_cast<float4*>(base + (plane ? BLO_OFF : BHI_OFF) + off) = bP[i];
        }
        __syncthreads();     // single barrier per chunk (see header comment)

        // prefetch t+1
        if (t + 1 < T) {
            int kt = (t + 1) << 6;
            #pragma unroll
            for (int i = 0; i < 4; i++) {
                int f = tid + (i << 9);
                int plane = f >> 10, rem = f & 1023;
                int row = rem >> 3, kc = rem & 7;
                const __nv_bfloat16* Ap = plane ? Alo : Ahi;
                aP[i] = *reinterpret_cast<const float4*>((const char*)(Ap + (size_t)(bm + row) * K + kt) + kc * 16);
                const __nv_bfloat16* Wp = plane ? Wlo : Whi;
                if (bn + row < N)
                    bP[i] = *reinterpret_cast<const float4*>((const char*)(Wp + (size_t)(bn + row) * K + kt) + kc * 16);
                else
                    bP[i] = make_float4(0.f, 0.f, 0.f, 0.f);
            }
        }

        // compute 4 k16-steps with B-fragment double buffering
        uint32_t bh[2][4][2], bl[2][4][2];
        #pragma unroll
        for (int p = 0; p < 2; p++) {
            LDMX4(bh[0][2 * p][0], bh[0][2 * p][1], bh[0][2 * p + 1][0], bh[0][2 * p + 1][1],
                  sbase + BHI_OFF + bBase + p * (16 * RSTRIDE));
            LDMX4(bl[0][2 * p][0], bl[0][2 * p][1], bl[0][2 * p + 1][0], bl[0][2 * p + 1][1],
                  sbase + BLO_OFF + bBase + p * (16 * RSTRIDE));
        }
        #pragma unroll
        for (int ks = 0; ks < 4; ks++) {
            int cur = ks & 1, nxt = cur ^ 1;
            if (ks < 3) {
                int k2n = (ks + 1) * 32;
                #pragma unroll
                for (int p = 0; p < 2; p++) {
                    LDMX4(bh[nxt][2 * p][0], bh[nxt][2 * p][1], bh[nxt][2 * p + 1][0], bh[nxt][2 * p + 1][1],
                          sbase + BHI_OFF + bBase + p * (16 * RSTRIDE) + k2n);
                    LDMX4(bl[nxt][2 * p][0], bl[nxt][2 * p][1], bl[nxt][2 * p + 1][0], bl[nxt][2 * p + 1][1],
                          sbase + BLO_OFF + bBase + p * (16 * RSTRIDE) + k2n);
                }
            }
            int k2 = ks * 32;
            uint32_t ah[2][4], al[2][4];
            #pragma unroll
            for (int mi = 0; mi < 2; mi++) {
                LDMX4(ah[mi][0], ah[mi][1], ah[mi][2], ah[mi][3],
                      sbase + AHI_OFF + aBase + mi * (16 * RSTRIDE) + k2);
                LDMX4(al[mi][0], al[mi][1], al[mi][2], al[mi][3],
                      sbase + ALO_OFF + aBase + mi * (16 * RSTRIDE) + k2);
            }
            #pragma unroll
            for (int mi = 0; mi < 2; mi++) {
                #pragma unroll
                for (int ni = 0; ni < 4; ni++) {
                    MMA_BF16(acc[mi][ni], ah[mi][0], ah[mi][1], ah[mi][2], ah[mi][3],
                             bh[cur][ni][0], bh[cur][ni][1]);
                    MMA_BF16(acc[mi][ni], ah[mi][0], ah[mi][1], ah[mi][2], ah[mi][3],
                             bl[cur][ni][0], bl[cur][ni][1]);
                    MMA_BF16(acc[mi][ni], al[mi][0], al[mi][1], al[mi][2], al[mi][3],
                             bh[cur][ni][0], bh[cur][ni][1]);
                }
            }
        }
        // no end-of-chunk sync: double buffer + program order make it redundant
    }

    // epilogue
    #pragma unroll
    for (int mi = 0; mi < 2; mi++) {
        int gm0 = bm + wm * 32 + mi * 16 + gid;
        #pragma unroll
        for (int ni = 0; ni < 4; ni++) {
            int gc = bn + wn * 32 + ni * 8 + 2 * ctid;
            if (gc < N) {
                float bx = 0.f, by = 0.f;
                if (bias) { bx = bias[gc]; by = bias[gc + 1]; }
                float v0 = acc[mi][ni][0] + bx, v1 = acc[mi][ni][1] + by;
                float v2 = acc[mi][ni][2] + bx, v3 = acc[mi][ni][3] + by;
                if (relu) {
                    v0 = fmaxf(v0, 0.f); v1 = fmaxf(v1, 0.f);
                    v2 = fmaxf(v2, 0.f); v3 = fmaxf(v3, 0.f);
                }
                if (splitout) {
                    __nv_bfloat16* Chi = (__nv_bfloat16*)Cptr;
                    __nv_bfloat16* Clo = Chi + PLANE;
                    uint32_t h01 = pack_bf2(v0, v1);
                    uint32_t h23 = pack_bf2(v2, v3);
                    float r0 = v0 - __uint_as_float(h01 << 16);
                    float r1 = v1 - __uint_as_float(h01 & 0xFFFF0000u);
                    float r2 = v2 - __uint_as_float(h23 << 16);
                    float r3 = v3 - __uint_as_float(h23 & 0xFFFF0000u);
                    *reinterpret_cast<uint32_t*>(Chi + (size_t)gm0 * N + gc) = h01;
                    *reinterpret_cast<uint32_t*>(Clo + (size_t)gm0 * N + gc) = pack_bf2(r0, r1);
                    *reinterpret_cast<uint32_t*>(Chi + (size_t)(gm0 + 8) * N + gc) = h23;
                    *reinterpret_cast<uint32_t*>(Clo + (size_t)(gm0 + 8) * N + gc) = pack_bf2(r2, r3);
                } else {
                    float* C = (float*)Cptr;
                    *reinterpret_cast<float2*>(C + (size_t)gm0 * N + gc) = make_float2(v0, v1);
                    *reinterpret_cast<float2*>(C + (size_t)(gm0 + 8) * N + gc) = make_float2(v2, v3);
                }
            }
        }
    }
}

// ---------------- GCN aggregate on split planes ----------------
__device__ __forceinline__ void unpack8(uint4 h, uint4 l, float* v) {
    const uint32_t* hp = (const uint32_t*)&h;
    const uint32_t* lp = (const uint32_t*)&l;
    #pragma unroll
    for (int j = 0; j < 4; j++) {
        v[2 * j]     = __uint_as_float(hp[j] << 16)        + __uint_as_float(lp[j] << 16);
        v[2 * j + 1] = __uint_as_float(hp[j] & 0xFFFF0000u) + __uint_as_float(lp[j] & 0xFFFF0000u);
    }
}

__global__ void k_agg(const __nv_bfloat16* __restrict__ H, __nv_bfloat16* __restrict__ X,
                      const float* __restrict__ bias, int Cout, int relu) {
    int n = blockIdx.y;
    int C8 = (NB * Cout) >> 3;   // 16B groups per node-row
    int i = blockIdx.x * blockDim.x + threadIdx.x;
    if (i >= C8) return;
    const uint4* Hh = (const uint4*)H;
    const uint4* Hl = (const uint4*)(H + PLANE);
    uint4* Xh = (uint4*)X;
    uint4* Xl = (uint4*)(X + PLANE);

    float acc[8];
    float sw = g_selfw[n];
    size_t base = (size_t)n * C8 + i;
    {
        float v[8];
        unpack8(Hh[base], Hl[base], v);
        if (bias) {
            int b = (8 * i) / Cout;
            int c0 = 8 * i - b * Cout;
            #pragma unroll
            for (int j = 0; j < 8; j++) acc[j] = v[j] * sw + bias[c0 + j];
        } else {
            #pragma unroll
            for (int j = 0; j < 8; j++) acc[j] = v[j] * sw;
        }
    }
    int e0 = g_rowptr[n], e1 = g_rowptr[n + 1];
    for (int e = e0; e < e1; e++) {
        int s = g_csrc[e];
        float w = g_cw[e];
        float v[8];
        unpack8(Hh[(size_t)s * C8 + i], Hl[(size_t)s * C8 + i], v);
        #pragma unroll
        for (int j = 0; j < 8; j++) acc[j] += v[j] * w;
    }
    if (relu) {
        #pragma unroll
        for (int j = 0; j < 8; j++) acc[j] = fmaxf(acc[j], 0.0f);
    }
    uint4 oh, ol;
    uint32_t* ohp = (uint32_t*)&oh;
    uint32_t* olp = (uint32_t*)&ol;
    #pragma unroll
    for (int j = 0; j < 4; j++) {
        uint32_t hp_ = pack_bf2(acc[2 * j], acc[2 * j + 1]);
        float r0 = acc[2 * j]     - __uint_as_float(hp_ << 16);
        float r1 = acc[2 * j + 1] - __uint_as_float(hp_ & 0xFFFF0000u);
        ohp[j] = hp_;
        olp[j] = pack_bf2(r0, r1);
    }
    Xh[base] = oh;
    Xl[base] = ol;
}

// ---------------- head layer 3 ----------------
__global__ void k_head3(const float* __restrict__ D, const float* __restrict__ W3,
                        const float* __restrict__ b3, const float* __restrict__ V,
                        float* __restrict__ out) {
    int r = blockIdx.x * blockDim.x + threadIdx.x;
    if (r >= MROWS) return;
    int n = r >> 2, b = r & 3;
    const float* d = D + (size_t)r * 64;
    float y0 = b3[0], y1 = b3[1], y2 = b3[2];
    #pragma unroll 8
    for (int c = 0; c < 64; c++) {
        float v = d[c];
        y0 += v * W3[c * 3 + 0];
        y1 += v * W3[c * 3 + 1];
        y2 += v * W3[c * 3 + 2];
    }
    float ys[3] = {y0, y1, y2};
    #pragma unroll
    for (int k = 0; k < 3; k++) {
        float y = tanhf(ys[k]);
        if (isnan(y)) y = 0.0f;
        y = fminf(fmaxf(y, -2.5f), 2.5f);
        out[((size_t)b * NV + n) * 3 + k] = V[n * 3 + k] + y;
    }
}

// ---------------- host driver ----------------
extern "C" void kernel_launch(void* const* d_in, const int* in_sizes, int n_in,
                              void* d_out, int out_size) {
    const float* feat  = (const float*)d_in[0];
    const float* verts = (const float*)d_in[1];
    const int*   eidx  = (const int*)d_in[2];
    int E = in_sizes[2] / 2;
    if (E > MAXE) E = MAXE;
    const int* esrc = eidx;
    const int* edst = eidx + E;
    const float* encW1 = (const float*)d_in[3];
    const float* encb1 = (const float*)d_in[4];
    const float* encW2 = (const float*)d_in[5];
    const float* encb2 = (const float*)d_in[6];
    const float* gW[6] = {(const float*)d_in[7],  (const float*)d_in[9],
                          (const float*)d_in[11], (const float*)d_in[13],
                          (const float*)d_in[15], (const float*)d_in[17]};
    const float* gb[6] = {(const float*)d_in[8],  (const float*)d_in[10],
                          (const float*)d_in[12], (const float*)d_in[14],
                          (const float*)d_in[16], (const float*)d_in[18]};
    const float* hW1 = (const float*)d_in[19];
    const float* hb1 = (const float*)d_in[20];
    const float* hW2 = (const float*)d_in[21];
    const float* hb2 = (const float*)d_in[22];
    const float* hW3 = (const float*)d_in[23];
    const float* hb3 = (const float*)d_in[24];

    __nv_bfloat16 *actA, *actB, *actC, *wthi, *wtlo;
    float* f32buf;
    cudaGetSymbolAddress((void**)&actA, g_actA);
    cudaGetSymbolAddress((void**)&actB, g_actB);
    cudaGetSymbolAddress((void**)&actC, g_actC);
    cudaGetSymbolAddress((void**)&f32buf, g_f32);
    cudaGetSymbolAddress((void**)&wthi, g_WThi);
    cudaGetSymbolAddress((void**)&wtlo, g_WTlo);

    cudaFuncSetAttribute(k_gemm, cudaFuncAttributeMaxDynamicSharedMemorySize, GEMM_SMEM);

    const int woff[9] = {0, 32768, 65536, 196608, 720896, 1245184, 1376256, 1409024, 1425408};
    const int wk[9]   = {256, 128, 256, 512, 1024, 512, 256, 128, 128};
    const int wn[9]   = {128, 256, 512, 1024, 512, 256, 128, 128, 64};
    const float* wptr[9] = {encW2, gW[0], gW[1], gW[2], gW[3], gW[4], gW[5], hW1, hW2};

    auto gemm = [&](const __nv_bfloat16* A, int li, void* C, const float* bias,
                    int relu, int splitout) {
        dim3 grid((wn[li] + 127) / 128, MTILES);
        k_gemm<<<grid, 512, GEMM_SMEM>>>(A, wthi + woff[li], wtlo + woff[li], C,
                                         wk[li], wn[li], bias, relu, splitout);
    };
    auto agg = [&](const __nv_bfloat16* H, __nv_bfloat16* X, const float* bias,
                   int Cout, int relu) {
        int C8 = (NB * Cout) >> 3;
        k_agg<<<dim3((C8 + 127) / 128, NV), 128>>>(H, X, bias, Cout, relu);
    };

    // launch order: #4 = first big GEMM (ncu capture window)
    k_prep<<<1, 1024>>>(feat, encW1, encb1);                                  // 1
    k_wsplit<<<(wn[0] * wk[0] + 255) / 256, 256>>>(wptr[0], wk[0], wn[0],
                                                   wthi + woff[0], wtlo + woff[0]); // 2
    k_enc1<<<MROWS, 256>>>(verts, encW1);                                     // 3
    gemm(actA, 0, actB, encb2, 1, 1);                                         // 4 (profiled)

    for (int li = 1; li < 9; li++)
        k_wsplit<<<(wn[li] * wk[li] + 255) / 256, 256>>>(wptr[li], wk[li], wn[li],
                                                         wthi + woff[li], wtlo + woff[li]);
    k_zero<<<(NV + 255) / 256, 256>>>();
    k_count<<<(E + 255) / 256, 256>>>(edst, E);
    k_scan<<<1, 1024>>>();
    k_dinv<<<(NV + 255) / 256, 256>>>();
    k_fill<<<(E + 255) / 256, 256>>>(esrc, edst, E);
    k_sort<<<(NV + 255) / 256, 256>>>();

    // g1..g3: aggregate-then-GEMM (Cin < Cout); bias+relu fused in GEMM
    agg(actB, actC, (const float*)0, 128, 0);
    gemm(actC, 1, actA, gb[0], 1, 1);
    agg(actA, actB, (const float*)0, 256, 0);
    gemm(actB, 2, actC, gb[1], 1, 1);
    agg(actC, actA, (const float*)0, 512, 0);
    gemm(actA, 3, actB, gb[2], 1, 1);
    // g4..g6: GEMM-then-aggregate (Cout < Cin); bias+relu fused in aggregate
    gemm(actB, 4, actC, (const float*)0, 0, 1);
    agg(actC, actA, gb[3], 512, 1);
    gemm(actA, 5, actB, (const float*)0, 0, 1);
    agg(actB, actC, gb[4], 256, 1);
    gemm(actC, 6, actA, (const float*)0, 0, 1);
    agg(actA, actB, gb[5], 128, 1);
    // head
    gemm(actB, 7, actC, hb1, 1, 1);
    gemm(actC, 8, f32buf, hb2, 1, 0);
    k_head3<<<(MROWS + 255) / 256, 256>>>(f32buf, hW3, hb3, verts, (float*)d_out);
}

// round 15
// speedup vs baseline: 1.1652x; 1.0263x over previous
#include <cuda_runtime.h>
#include <cuda_bf16.h>
#include <math.h>
#include <stdint.h>

#define NV 20000
#define NB 4
#define NCF 64
#define VOX 64
#define MROWS (NV*NB)      // 80000
#define MTILES (MROWS/128) // 625
#define MAXW 1024
#define MAXE 131072
#define WT_TOTAL 1433600
#define PLANE ((size_t)MROWS * MAXW)   // bf16 elements per plane

// ---------------- static device scratch ----------------
__device__ __align__(16) __nv_bfloat16 g_actA[2 * PLANE];   // hi plane, lo plane
__device__ __align__(16) __nv_bfloat16 g_actB[2 * PLANE];
__device__ __align__(16) __nv_bfloat16 g_actC[2 * PLANE];
__device__ __align__(16) float g_f32[(size_t)MROWS * 64];
__device__ __align__(16) float g_off[NB * 256];
__device__ __align__(16) __nv_bfloat16 g_WThi[WT_TOTAL];
__device__ __align__(16) __nv_bfloat16 g_WTlo[WT_TOTAL];
__device__ int   g_cnt[NV];
__device__ int   g_cur[NV];
__device__ int   g_rowptr[NV + 1];
__device__ float g_dinv[NV];
__device__ float g_selfw[NV];
__device__ int   g_csrc[MAXE];
__device__ float g_cw[MAXE];

// ---------------- helpers ----------------
__device__ __forceinline__ uint32_t smem_u32(const void* p) {
    uint32_t a;
    asm("{ .reg .u64 t; cvta.to.shared.u64 t, %1; cvt.u32.u64 %0, t; }" : "=r"(a) : "l"(p));
    return a;
}
__device__ __forceinline__ uint32_t pack_bf2(float a, float b) {
    return (uint32_t)__bfloat16_as_ushort(__float2bfloat16_rn(a)) |
           ((uint32_t)__bfloat16_as_ushort(__float2bfloat16_rn(b)) << 16);
}

#define LDMX4(R0, R1, R2, R3, addr)                                              \
    asm volatile("ldmatrix.sync.aligned.m8n8.x4.shared.b16 {%0,%1,%2,%3}, [%4];" \
                 : "=r"(R0), "=r"(R1), "=r"(R2), "=r"(R3) : "r"(addr))

#define MMA_BF16(C, A0, A1, A2, A3, B0, B1)                                      \
    asm volatile("mma.sync.aligned.m16n8k16.row.col.f32.bf16.bf16.f32 "          \
                 "{%0,%1,%2,%3}, {%4,%5,%6,%7}, {%8,%9}, {%0,%1,%2,%3};"         \
                 : "+f"((C)[0]), "+f"((C)[1]), "+f"((C)[2]), "+f"((C)[3])        \
                 : "r"(A0), "r"(A1), "r"(A2), "r"(A3), "r"(B0), "r"(B1))

// ---------------- prep: constant voxel sample + encoder-1 offset ----------------
__global__ void k_prep(const float* __restrict__ feat, const float* __restrict__ W1,
                       const float* __restrict__ b1) {
    __shared__ float s[NB * NCF];
    int t = threadIdx.x;   // 1024
    if (t < NB * NCF) {
        int b = t / NCF, c = t % NCF;
        float vn = -1.0f / 1.5f;
        float x = (vn + 1.0f) * 0.5f * (float)(VOX - 1);
        x = fminf(fmaxf(x, 0.0f), (float)(VOX - 1));
        float x0f = floorf(x);
        float w = x - x0f;
        int i0 = (int)x0f;
        if (i0 < 0) i0 = 0;
        if (i0 > VOX - 1) i0 = VOX - 1;
        int i1 = i0 + 1;
        if (i1 > VOX - 1) i1 = VOX - 1;
        const float* f = feat + (size_t)(b * NCF + c) * VOX * VOX * VOX;
        #define FV(z, y, xx) f[((z) * VOX + (y)) * VOX + (xx)]
        float c00 = FV(i0, i0, i0) * (1.0f - w) + FV(i0, i0, i1) * w;
        float c01 = FV(i0, i1, i0) * (1.0f - w) + FV(i0, i1, i1) * w;
        float c10 = FV(i1, i0, i0) * (1.0f - w) + FV(i1, i0, i1) * w;
        float c11 = FV(i1, i1, i0) * (1.0f - w) + FV(i1, i1, i1) * w;
        #undef FV
        float c0 = c00 * (1.0f - w) + c01 * w;
        float c1 = c10 * (1.0f - w) + c11 * w;
        s[t] = c0 * (1.0f - w) + c1 * w;
    }
    __syncthreads();
    int b = t >> 8, j = t & 255;
    float acc = b1[j];
    #pragma unroll 8
    for (int c = 0; c < NCF; c++)
        acc += s[b * NCF + c] * W1[(3 + c) * 256 + j];
    g_off[t] = acc;
}

// encoder layer 1: writes split bf16 planes into g_actA (K=256)
__global__ void k_enc1(const float* __restrict__ V, const float* __restrict__ W1) {
    int row = blockIdx.x;
    int j = threadIdx.x;
    int n = row >> 2, b = row & 3;
    float vx = V[n * 3 + 0], vy = V[n * 3 + 1], vz = V[n * 3 + 2];
    float acc = g_off[b * 256 + j] + vx * W1[j] + vy * W1[256 + j] + vz * W1[512 + j];
    acc = fmaxf(acc, 0.0f);
    __nv_bfloat16 h = __float2bfloat16_rn(acc);
    g_actA[(size_t)row * 256 + j] = h;
    g_actA[PLANE + (size_t)row * 256 + j] = __float2bfloat16_rn(acc - __bfloat162float(h));
}

// ---------------- weight transpose + bf16 hi/lo split (coalesced tile transpose) ----------------
// out[n][k] = W[k][n]; 32x32 smem tile, both sides coalesced.
__global__ void k_wsplit(const float* __restrict__ W, int K, int N,
                         __nv_bfloat16* __restrict__ hi, __nv_bfloat16* __restrict__ lo) {
    __shared__ float tile[32][33];
    int tx = threadIdx.x, ty = threadIdx.y;     // block (32, 8)
    int n0 = blockIdx.x * 32, k0 = blockIdx.y * 32;
    #pragma unroll
    for (int i = 0; i < 4; i++) {
        int k = k0 + ty + i * 8, n = n0 + tx;
        if (k < K && n < N) tile[ty + i * 8][tx] = W[(size_t)k * N + n];
    }
    __syncthreads();
    #pragma unroll
    for (int i = 0; i < 4; i++) {
        int n = n0 + ty + i * 8, k = k0 + tx;
        if (n < N && k < K) {
            float v = tile[tx][ty + i * 8];
            __nv_bfloat16 h = __float2bfloat16_rn(v);
            hi[(size_t)n * K + k] = h;
            lo[(size_t)n * K + k] = __float2bfloat16_rn(v - __bfloat162float(h));
        }
    }
}

// ---------------- graph preprocessing ----------------
__global__ void k_zero() {
    int i = blockIdx.x * 256 + threadIdx.x;
    if (i < NV) { g_cnt[i] = 0; g_cur[i] = 0; }
}
__global__ void k_count(const int* __restrict__ dst, int E) {
    int e = blockIdx.x * 256 + threadIdx.x;
    if (e < E) atomicAdd(&g_cnt[dst[e]], 1);
}
__global__ void k_scan() {
    __shared__ int part[1024];
    int t = threadIdx.x;
    const int SEG = 20;
    int base = t * SEG;
    int s = 0;
    for (int i = 0; i < SEG; i++) {
        int idx = base + i;
        if (idx < NV) s += g_cnt[idx];
    }
    part[t] = s;
    __syncthreads();
    for (int off = 1; off < 1024; off <<= 1) {
        int v = (t >= off) ? part[t - off] : 0;
        __syncthreads();
        part[t] += v;
        __syncthreads();
    }
    int run = (t == 0) ? 0 : part[t - 1];
    for (int i = 0; i < SEG; i++) {
        int idx = base + i;
        if (idx < NV) { g_rowptr[idx] = run; run += g_cnt[idx]; }
    }
    if (t == 1023) g_rowptr[NV] = part[1023];
}
__global__ void k_dinv() {
    int n = blockIdx.x * 256 + threadIdx.x;
    if (n < NV) {
        float d = (float)g_cnt[n] + 1.0f;
        float di = 1.0f / sqrtf(d);
        g_dinv[n] = di;
        g_selfw[n] = di * di;
    }
}
__global__ void k_fill(const int* __restrict__ src, const int* __restrict__ dst, int E) {
    int e = blockIdx.x * 256 + threadIdx.x;
    if (e >= E) return;
    int s = src[e], d = dst[e];
    int slot = atomicAdd(&g_cur[d], 1);
    int p = g_rowptr[d] + slot;
    g_csrc[p] = s;
    g_cw[p] = g_dinv[s] * g_dinv[d];
}
__global__ void k_sort() {
    int n = blockIdx.x * 256 + threadIdx.x;
    if (n >= NV) return;
    int a = g_rowptr[n], bnd = g_rowptr[n + 1];
    for (int i = a + 1; i < bnd; i++) {
        int key = g_csrc[i]; float kw = g_cw[i];
        int j = i - 1;
        while (j >= a && g_csrc[j] > key) {
            g_csrc[j + 1] = g_csrc[j]; g_cw[j + 1] = g_cw[j]; j--;
        }
        g_csrc[j + 1] = key; g_cw[j + 1] = kw;
    }
}

// ---------------- bf16x3 mma GEMM: persistent M-loop, 128x128, 16 warps @ 32x32, BK=64 ----------------
// A: split bf16 planes [M][K] (hi at Abase, lo at Abase+PLANE). W: split [N][K].
// Each CTA owns one N-tile and strides over M-tiles (grid.x*grid.y <= 148 -> 1 CTA/SM);
// next tile's chunk-0 LDGs are issued before the epilogue so STG overlaps the next prolog.
// All K/64 chunk counts are even -> inter-tile double-buffer parity is race-free.
#define RSTRIDE 144
#define AHI_OFF 0
#define ALO_OFF 18432
#define BHI_OFF 36864
#define BLO_OFF 55296
#define STAGEB  73728
#define GEMM_SMEM (2 * STAGEB)

__global__ __launch_bounds__(512, 1)
void k_gemm(const __nv_bfloat16* __restrict__ Abase, const __nv_bfloat16* __restrict__ Whi,
            const __nv_bfloat16* __restrict__ Wlo, void* __restrict__ Cptr,
            int K, int N, const float* __restrict__ bias, int relu, int splitout) {
    extern __shared__ char smem[];
    uint32_t sb = smem_u32(smem);
    const __nv_bfloat16* Ahi = Abase;
    const __nv_bfloat16* Alo = Abase + PLANE;
    int tid = threadIdx.x;
    int warp = tid >> 5, lane = tid & 31;
    int gid = lane >> 2, ctid = lane & 3;
    int wm = warp & 3;       // 4 slabs of 32 rows
    int wn = warp >> 2;      // 4 slabs of 32 cols
    int bn = blockIdx.x * 128;

    // ldmatrix lane addressing
    int aLr = (lane & 7) + ((lane >> 3) & 1) * 8;
    int aLk = (lane >> 4) * 16;
    int aBase = (wm * 32 + aLr) * RSTRIDE + aLk;
    int bLr = (lane & 7) + (lane >> 4) * 8;
    int bLk = ((lane >> 3) & 1) * 16;
    int bBase = (wn * 32 + bLr) * RSTRIDE + bLk;

    // per-thread staging coordinates
    int sf[4], s_plane[4], s_row[4], s_kc[4];
    #pragma unroll
    for (int i = 0; i < 4; i++) {
        sf[i] = tid + (i << 9);
        s_plane[i] = sf[i] >> 10;
        int rem = sf[i] & 1023;
        s_row[i] = rem >> 3;
        s_kc[i] = rem & 7;
    }

    float4 aP[4], bP[4];
    auto prefetch = [&](int bm, int kt) {
        #pragma unroll
        for (int i = 0; i < 4; i++) {
            const __nv_bfloat16* Ap = s_plane[i] ? Alo : Ahi;
            aP[i] = *reinterpret_cast<const float4*>(
                (const char*)(Ap + (size_t)(bm + s_row[i]) * K + kt) + s_kc[i] * 16);
            const __nv_bfloat16* Wp = s_plane[i] ? Wlo : Whi;
            if (bn + s_row[i] < N)
                bP[i] = *reinterpret_cast<const float4*>(
                    (const char*)(Wp + (size_t)(bn + s_row[i]) * K + kt) + s_kc[i] * 16);
            else
                bP[i] = make_float4(0.f, 0.f, 0.f, 0.f);
        }
    };

    int T = K >> 6;
    int mt = blockIdx.y;
    if (mt < MTILES) prefetch(mt * 128, 0);

    for (; mt < MTILES; mt += gridDim.y) {
        int bm = mt * 128;
        float acc[2][4][4];
        #pragma unroll
        for (int i = 0; i < 2; i++)
            #pragma unroll
            for (int j = 0; j < 4; j++)
                #pragma unroll
                for (int f = 0; f < 4; f++) acc[i][j][f] = 0.0f;

        for (int t = 0; t < T; t++) {
            char* base = smem + (t & 1) * STAGEB;
            uint32_t sbase = sb + (t & 1) * STAGEB;
            #pragma unroll
            for (int i = 0; i < 4; i++) {
                int off = s_row[i] * RSTRIDE + s_kc[i] * 16;
                *reinterpret_cast<float4*>(base + (s_plane[i] ? ALO_OFF : AHI_OFF) + off) = aP[i];
                *reinterpret_cast<float4*>(base + (s_plane[i] ? BLO_OFF : BHI_OFF) + off) = bP[i];
            }
            __syncthreads();

            if (t + 1 < T) prefetch(bm, (t + 1) << 6);

            #pragma unroll
            for (int ks = 0; ks < 4; ks++) {
                int k2 = ks * 32;
                uint32_t bh[4][2], bl[4][2];
                #pragma unroll
                for (int p = 0; p < 2; p++) {
                    LDMX4(bh[2 * p][0], bh[2 * p][1], bh[2 * p + 1][0], bh[2 * p + 1][1],
                          sbase + BHI_OFF + bBase + p * (16 * RSTRIDE) + k2);
                    LDMX4(bl[2 * p][0], bl[2 * p][1], bl[2 * p + 1][0], bl[2 * p + 1][1],
                          sbase + BLO_OFF + bBase + p * (16 * RSTRIDE) + k2);
                }
                #pragma unroll
                for (int mi = 0; mi < 2; mi++) {
                    uint32_t ah[4], al[4];
                    LDMX4(ah[0], ah[1], ah[2], ah[3],
                          sbase + AHI_OFF + aBase + mi * (16 * RSTRIDE) + k2);
                    LDMX4(al[0], al[1], al[2], al[3],
                          sbase + ALO_OFF + aBase + mi * (16 * RSTRIDE) + k2);
                    #pragma unroll
                    for (int ni = 0; ni < 4; ni++) {
                        MMA_BF16(acc[mi][ni], ah[0], ah[1], ah[2], ah[3], bh[ni][0], bh[ni][1]);
                        MMA_BF16(acc[mi][ni], ah[0], ah[1], ah[2], ah[3], bl[ni][0], bl[ni][1]);
                        MMA_BF16(acc[mi][ni], al[0], al[1], al[2], al[3], bh[ni][0], bh[ni][1]);
                    }
                }
            }
            if (t + 1 < T) __syncthreads();
        }

        // issue next tile's prolog before the epilogue (overlap STG with LDG)
        int mtn = mt + gridDim.y;
        if (mtn < MTILES) prefetch(mtn * 128, 0);

        // epilogue
        #pragma unroll
        for (int mi = 0; mi < 2; mi++) {
            int gm0 = bm + wm * 32 + mi * 16 + gid;
            #pragma unroll
            for (int ni = 0; ni < 4; ni++) {
                int gc = bn + wn * 32 + ni * 8 + 2 * ctid;
                if (gc < N) {
                    float bx = 0.f, by = 0.f;
                    if (bias) { bx = bias[gc]; by = bias[gc + 1]; }
                    float v0 = acc[mi][ni][0] + bx, v1 = acc[mi][ni][1] + by;
                    float v2 = acc[mi][ni][2] + bx, v3 = acc[mi][ni][3] + by;
                    if (relu) {
                        v0 = fmaxf(v0, 0.f); v1 = fmaxf(v1, 0.f);
                        v2 = fmaxf(v2, 0.f); v3 = fmaxf(v3, 0.f);
                    }
                    if (splitout) {
                        __nv_bfloat16* Chi = (__nv_bfloat16*)Cptr;
                        __nv_bfloat16* Clo = Chi + PLANE;
                        uint32_t h01 = pack_bf2(v0, v1);
                        uint32_t h23 = pack_bf2(v2, v3);
                        float r0 = v0 - __uint_as_float(h01 << 16);
                        float r1 = v1 - __uint_as_float(h01 & 0xFFFF0000u);
                        float r2 = v2 - __uint_as_float(h23 << 16);
                        float r3 = v3 - __uint_as_float(h23 & 0xFFFF0000u);
                        *reinterpret_cast<uint32_t*>(Chi + (size_t)gm0 * N + gc) = h01;
                        *reinterpret_cast<uint32_t*>(Clo + (size_t)gm0 * N + gc) = pack_bf2(r0, r1);
                        *reinterpret_cast<uint32_t*>(Chi + (size_t)(gm0 + 8) * N + gc) = h23;
                        *reinterpret_cast<uint32_t*>(Clo + (size_t)(gm0 + 8) * N + gc) = pack_bf2(r2, r3);
                    } else {
                        float* C = (float*)Cptr;
                        *reinterpret_cast<float2*>(C + (size_t)gm0 * N + gc) = make_float2(v0, v1);
                        *reinterpret_cast<float2*>(C + (size_t)(gm0 + 8) * N + gc) = make_float2(v2, v3);
                    }
                }
            }
        }
    }
}

// ---------------- GCN aggregate on split planes ----------------
__device__ __forceinline__ void unpack8(uint4 h, uint4 l, float* v) {
    const uint32_t* hp = (const uint32_t*)&h;
    const uint32_t* lp = (const uint32_t*)&l;
    #pragma unroll
    for (int j = 0; j < 4; j++) {
        v[2 * j]     = __uint_as_float(hp[j] << 16)        + __uint_as_float(lp[j] << 16);
        v[2 * j + 1] = __uint_as_float(hp[j] & 0xFFFF0000u) + __uint_as_float(lp[j] & 0xFFFF0000u);
    }
}

__global__ void k_agg(const __nv_bfloat16* __restrict__ H, __nv_bfloat16* __restrict__ X,
                      const float* __restrict__ bias, int Cout, int relu) {
    int n = blockIdx.y;
    int C8 = (NB * Cout) >> 3;   // 16B groups per node-row
    int i = blockIdx.x * blockDim.x + threadIdx.x;
    if (i >= C8) return;
    const uint4* Hh = (const uint4*)H;
    const uint4* Hl = (const uint4*)(H + PLANE);
    uint4* Xh = (uint4*)X;
    uint4* Xl = (uint4*)(X + PLANE);

    float acc[8];
    float sw = g_selfw[n];
    size_t base = (size_t)n * C8 + i;
    {
        float v[8];
        unpack8(Hh[base], Hl[base], v);
        if (bias) {
            int b = (8 * i) / Cout;
            int c0 = 8 * i - b * Cout;
            #pragma unroll
            for (int j = 0; j < 8; j++) acc[j] = v[j] * sw + bias[c0 + j];
        } else {
            #pragma unroll
            for (int j = 0; j < 8; j++) acc[j] = v[j] * sw;
        }
    }
    int e0 = g_rowptr[n], e1 = g_rowptr[n + 1];
    for (int e = e0; e < e1; e++) {
        int s = g_csrc[e];
        float w = g_cw[e];
        float v[8];
        unpack8(Hh[(size_t)s * C8 + i], Hl[(size_t)s * C8 + i], v);
        #pragma unroll
        for (int j = 0; j < 8; j++) acc[j] += v[j] * w;
    }
    if (relu) {
        #pragma unroll
        for (int j = 0; j < 8; j++) acc[j] = fmaxf(acc[j], 0.0f);
    }
    uint4 oh, ol;
    uint32_t* ohp = (uint32_t*)&oh;
    uint32_t* olp = (uint32_t*)&ol;
    #pragma unroll
    for (int j = 0; j < 4; j++) {
        uint32_t hp_ = pack_bf2(acc[2 * j], acc[2 * j + 1]);
        float r0 = acc[2 * j]     - __uint_as_float(hp_ << 16);
        float r1 = acc[2 * j + 1] - __uint_as_float(hp_ & 0xFFFF0000u);
        ohp[j] = hp_;
        olp[j] = pack_bf2(r0, r1);
    }
    Xh[base] = oh;
    Xl[base] = ol;
}

// ---------------- head layer 3 ----------------
__global__ void k_head3(const float* __restrict__ D, const float* __restrict__ W3,
                        const float* __restrict__ b3, const float* __restrict__ V,
                        float* __restrict__ out) {
    int r = blockIdx.x * blockDim.x + threadIdx.x;
    if (r >= MROWS) return;
    int n = r >> 2, b = r & 3;
    const float* d = D + (size_t)r * 64;
    float y0 = b3[0], y1 = b3[1], y2 = b3[2];
    #pragma unroll 8
    for (int c = 0; c < 64; c++) {
        float v = d[c];
        y0 += v * W3[c * 3 + 0];
        y1 += v * W3[c * 3 + 1];
        y2 += v * W3[c * 3 + 2];
    }
    float ys[3] = {y0, y1, y2};
    #pragma unroll
    for (int k = 0; k < 3; k++) {
        float y = tanhf(ys[k]);
        if (isnan(y)) y = 0.0f;
        y = fminf(fmaxf(y, -2.5f), 2.5f);
        out[((size_t)b * NV + n) * 3 + k] = V[n * 3 + k] + y;
    }
}

// ---------------- host driver ----------------
extern "C" void kernel_launch(void* const* d_in, const int* in_sizes, int n_in,
                              void* d_out, int out_size) {
    const float* feat  = (const float*)d_in[0];
    const float* verts = (const float*)d_in[1];
    const int*   eidx  = (const int*)d_in[2];
    int E = in_sizes[2] / 2;
    if (E > MAXE) E = MAXE;
    const int* esrc = eidx;
    const int* edst = eidx + E;
    const float* encW1 = (const float*)d_in[3];
    const float* encb1 = (const float*)d_in[4];
    const float* encW2 = (const float*)d_in[5];
    const float* encb2 = (const float*)d_in[6];
    const float* gW[6] = {(const float*)d_in[7],  (const float*)d_in[9],
                          (const float*)d_in[11], (const float*)d_in[13],
                          (const float*)d_in[15], (const float*)d_in[17]};
    const float* gb[6] = {(const float*)d_in[8],  (const float*)d_in[10],
                          (const float*)d_in[12], (const float*)d_in[14],
                          (const float*)d_in[16], (const float*)d_in[18]};
    const float* hW1 = (const float*)d_in[19];
    const float* hb1 = (const float*)d_in[20];
    const float* hW2 = (const float*)d_in[21];
    const float* hb2 = (const float*)d_in[22];
    const float* hW3 = (const float*)d_in[23];
    const float* hb3 = (const float*)d_in[24];

    __nv_bfloat16 *actA, *actB, *actC, *wthi, *wtlo;
    float* f32buf;
    cudaGetSymbolAddress((void**)&actA, g_actA);
    cudaGetSymbolAddress((void**)&actB, g_actB);
    cudaGetSymbolAddress((void**)&actC, g_actC);
    cudaGetSymbolAddress((void**)&f32buf, g_f32);
    cudaGetSymbolAddress((void**)&wthi, g_WThi);
    cudaGetSymbolAddress((void**)&wtlo, g_WTlo);

    cudaFuncSetAttribute(k_gemm, cudaFuncAttributeMaxDynamicSharedMemorySize, GEMM_SMEM);

    const int woff[9] = {0, 32768, 65536, 196608, 720896, 1245184, 1376256, 1409024, 1425408};
    const int wk[9]   = {256, 128, 256, 512, 1024, 512, 256, 128, 128};
    const int wn[9]   = {128, 256, 512, 1024, 512, 256, 128, 128, 64};
    const float* wptr[9] = {encW2, gW[0], gW[1], gW[2], gW[3], gW[4], gW[5], hW1, hW2};

    auto wsplit = [&](int li) {
        dim3 grid((wn[li] + 31) / 32, (wk[li] + 31) / 32);
        k_wsplit<<<grid, dim3(32, 8)>>>(wptr[li], wk[li], wn[li],
                                        wthi + woff[li], wtlo + woff[li]);
    };
    auto gemm = [&](const __nv_bfloat16* A, int li, void* C, const float* bias,
                    int relu, int splitout) {
        int nt = (wn[li] + 127) / 128;
        int gy = 148 / nt;
        if (gy > MTILES) gy = MTILES;
        dim3 grid(nt, gy);
        k_gemm<<<grid, 512, GEMM_SMEM>>>(A, wthi + woff[li], wtlo + woff[li], C,
                                         wk[li], wn[li], bias, relu, splitout);
    };
    auto agg = [&](const __nv_bfloat16* H, __nv_bfloat16* X, const float* bias,
                   int Cout, int relu) {
        int C8 = (NB * Cout) >> 3;
        k_agg<<<dim3((C8 + 127) / 128, NV), 128>>>(H, X, bias, Cout, relu);
    };

    // launch order: #4 = first big GEMM (ncu capture window)
    k_prep<<<1, 1024>>>(feat, encW1, encb1);                                  // 1
    wsplit(0);                                                                // 2
    k_enc1<<<MROWS, 256>>>(verts, encW1);                                     // 3
    gemm(actA, 0, actB, encb2, 1, 1);                                         // 4 (profiled)

    for (int li = 1; li < 9; li++) wsplit(li);
    k_zero<<<(NV + 255) / 256, 256>>>();
    k_count<<<(E + 255) / 256, 256>>>(edst, E);
    k_scan<<<1, 1024>>>();
    k_dinv<<<(NV + 255) / 256, 256>>>();
    k_fill<<<(E + 255) / 256, 256>>>(esrc, edst, E);
    k_sort<<<(NV + 255) / 256, 256>>>();

    // g1..g3: aggregate-then-GEMM (Cin < Cout); bias+relu fused in GEMM
    agg(actB, actC, (const float*)0, 128, 0);
    gemm(actC, 1, actA, gb[0], 1, 1);
    agg(actA, actB, (const float*)0, 256, 0);
    gemm(actB, 2, actC, gb[1], 1, 1);
    agg(actC, actA, (const float*)0, 512, 0);
    gemm(actA, 3, actB, gb[2], 1, 1);
    // g4..g6: GEMM-then-aggregate (Cout < Cin); bias+relu fused in aggregate
    gemm(actB, 4, actC, (const float*)0, 0, 1);
    agg(actC, actA, gb[3], 512, 1);
    gemm(actA, 5, actB, (const float*)0, 0, 1);
    agg(actB, actC, gb[4], 256, 1);
    gemm(actC, 6, actA, (const float*)0, 0, 1);
    agg(actA, actB, gb[5], 128, 1);
    // head
    gemm(actB, 7, actC, hb1, 1, 1);
    gemm(actC, 8, f32buf, hb2, 1, 0);
    k_head3<<<(MROWS + 255) / 256, 256>>>(f32buf, hW3, hb3, verts, (float*)d_out);
}